// round 1
// baseline (speedup 1.0000x reference)
#include <cuda_runtime.h>
#include <cstdint>

#define NN 2304
#define BB 1024
#define FF 32
#define BM 128
#define BN 128
#define BK 32
#define KT (NN / BK)     // 72
#define JN (NN / BN)     // 18

// Scratch (device globals — no allocation allowed)
__device__ float g_err[2][(size_t)BB * NN];   // ping-pong activations (tf32-rounded bits in fp32)
__device__ float g_keep[FF * NN];             // 1.0 / 0.0 keep mask
__device__ float g_partial[JN * BB];          // per-(n-tile,row) running totals (deterministic)

__device__ __forceinline__ unsigned tf32r(float x) {
    unsigned u;
    asm("cvt.rna.tf32.f32 %0, %1;" : "=r"(u) : "f"(x));
    return u;
}

// XOR swizzle: 32 words per row, 8 float4-groups, group ^= (row & 7)
__device__ __forceinline__ int swz(int row, int k) {
    return ((((k >> 2) ^ (row & 7)) << 2) | (k & 3));
}

__global__ void init_kernel() {
    int i = blockIdx.x * blockDim.x + threadIdx.x;
    if (i < FF * NN) g_keep[i] = 1.0f;
    if (i < JN * BB) g_partial[i] = 0.0f;
}

__global__ void scatter_kernel(const int* __restrict__ sel) {
    int i = threadIdx.x;
    if (i < 256) {
        int f = sel[3 * i];
        int node = sel[3 * i + 1] * 64 + sel[3 * i + 2];
        g_keep[f * NN + node] = 0.0f;
    }
}

// err0 = biases[0] broadcast, masked; row sums into g_partial[0..BB)
__global__ void frame0_kernel(const float* __restrict__ biases, const int* __restrict__ cand) {
    int b = blockIdx.x;
    int cf = cand[3 * b];
    int cn = cand[3 * b + 1] * 64 + cand[3 * b + 2];
    float s = 0.f;
    for (int n = threadIdx.x; n < NN; n += blockDim.x) {
        float v = biases[n] * g_keep[n];
        if (cf == 0 && cn == n) v = 0.f;
        g_err[0][(size_t)b * NN + n] = __uint_as_float(tf32r(v));
        s += v;
    }
    __shared__ float red[8];
    #pragma unroll
    for (int o = 16; o; o >>= 1) s += __shfl_xor_sync(0xffffffffu, s, o);
    if ((threadIdx.x & 31) == 0) red[threadIdx.x >> 5] = s;
    __syncthreads();
    if (threadIdx.x == 0) {
        float t = 0.f;
        #pragma unroll
        for (int w = 0; w < 8; w++) t += red[w];
        g_partial[b] += t;
    }
}

// One frame: dst = mask( bias_f + src @ W_f^T ), partial row sums accumulated.
__global__ void __launch_bounds__(256, 1)
gemm_frame(const float* __restrict__ weights,
           const float* __restrict__ biases,
           const int* __restrict__ cand,
           int f)
{
    extern __shared__ float smem[];             // [2][128][32] A then [2][128][32] B = 64 KB
    float* As = smem;
    float* Bs = smem + 2 * BM * BK;

    const float* __restrict__ Wf    = weights + (size_t)(f - 1) * NN * NN;  // [NN][NN] (n,k)
    const float* __restrict__ biasf = biases + (size_t)f * NN;
    const float* __restrict__ keepf = g_keep + f * NN;
    const float* __restrict__ src   = g_err[(f + 1) & 1];
    float* __restrict__ dst         = g_err[f & 1];

    int tid = threadIdx.x;
    int lane = tid & 31, warp = tid >> 5;
    int g = lane >> 2, c = lane & 3;
    int wm = warp >> 2, wn = warp & 3;          // 2x4 warp grid; warp tile 64x32
    int bm = blockIdx.x * BM;
    int bn = blockIdx.y * BN;

    // gmem->smem mapping: 4 float4 chunks per thread per tile
    int lrow = tid >> 3;                        // 0..31
    int lg = tid & 7;                           // float4 group within row
    const float* gA[4];
    const float* gB[4];
    uint32_t sA[4], sB[4];
    uint32_t asBase = (uint32_t)__cvta_generic_to_shared(As);
    uint32_t bsBase = (uint32_t)__cvta_generic_to_shared(Bs);
    #pragma unroll
    for (int i = 0; i < 4; i++) {
        int row = lrow + i * 32;
        gA[i] = src + (size_t)(bm + row) * NN + lg * 4;
        gB[i] = Wf + (size_t)(bn + row) * NN + lg * 4;
        int woff = row * BK + ((lg ^ (row & 7)) << 2);
        sA[i] = asBase + woff * 4;
        sB[i] = bsBase + woff * 4;
    }

    float acc[4][4][4];
    #pragma unroll
    for (int mi = 0; mi < 4; mi++)
        #pragma unroll
        for (int ni = 0; ni < 4; ni++)
            #pragma unroll
            for (int r = 0; r < 4; r++) acc[mi][ni][r] = 0.f;

    auto issue = [&](int kt) {
        uint32_t so = (uint32_t)(kt & 1) * BM * BK * 4;   // stage byte offset
        size_t go = (size_t)kt * BK;
        #pragma unroll
        for (int i = 0; i < 4; i++) {
            asm volatile("cp.async.cg.shared.global [%0], [%1], 16;\n"
                         :: "r"(sA[i] + so), "l"(gA[i] + go));
            asm volatile("cp.async.cg.shared.global [%0], [%1], 16;\n"
                         :: "r"(sB[i] + so), "l"(gB[i] + go));
        }
        asm volatile("cp.async.commit_group;\n");
    };

    issue(0);
    for (int kt = 0; kt < KT; ++kt) {
        asm volatile("cp.async.wait_group 0;\n" ::: "memory");
        __syncthreads();                          // publish stage kt; all done with other stage
        if (kt + 1 < KT) issue(kt + 1);           // overlaps compute(kt)
        const float* Asx = As + (kt & 1) * BM * BK;
        const float* Bsx = Bs + (kt & 1) * BM * BK;
        #pragma unroll
        for (int kk = 0; kk < 4; ++kk) {
            uint32_t a[4][4];
            #pragma unroll
            for (int mi = 0; mi < 4; ++mi) {
                int r0 = wm * 64 + mi * 16 + g;
                int k0 = kk * 8 + c;
                a[mi][0] = __float_as_uint(Asx[r0 * BK + swz(r0, k0)]);
                a[mi][1] = __float_as_uint(Asx[(r0 + 8) * BK + swz(r0 + 8, k0)]);
                a[mi][2] = __float_as_uint(Asx[r0 * BK + swz(r0, k0 + 4)]);
                a[mi][3] = __float_as_uint(Asx[(r0 + 8) * BK + swz(r0 + 8, k0 + 4)]);
            }
            uint32_t bf[4][2];
            #pragma unroll
            for (int ni = 0; ni < 4; ++ni) {
                int n0 = wn * 32 + ni * 8 + g;
                int k0 = kk * 8 + c;
                bf[ni][0] = tf32r(Bsx[n0 * BK + swz(n0, k0)]);
                bf[ni][1] = tf32r(Bsx[n0 * BK + swz(n0, k0 + 4)]);
            }
            #pragma unroll
            for (int mi = 0; mi < 4; ++mi)
                #pragma unroll
                for (int ni = 0; ni < 4; ++ni)
                    asm volatile(
                        "mma.sync.aligned.m16n8k8.row.col.f32.tf32.tf32.f32 "
                        "{%0,%1,%2,%3}, {%4,%5,%6,%7}, {%8,%9}, {%0,%1,%2,%3};\n"
                        : "+f"(acc[mi][ni][0]), "+f"(acc[mi][ni][1]),
                          "+f"(acc[mi][ni][2]), "+f"(acc[mi][ni][3])
                        : "r"(a[mi][0]), "r"(a[mi][1]), "r"(a[mi][2]), "r"(a[mi][3]),
                          "r"(bf[ni][0]), "r"(bf[ni][1]));
        }
    }
    __syncthreads();   // before reusing smem for reduction

    float* red = smem; // [4][128]
    #pragma unroll
    for (int mi = 0; mi < 4; ++mi) {
        int r0 = bm + wm * 64 + mi * 16 + g;
        int r1 = r0 + 8;
        int cf0 = cand[3 * r0], cn0 = cand[3 * r0 + 1] * 64 + cand[3 * r0 + 2];
        int cf1 = cand[3 * r1], cn1 = cand[3 * r1 + 1] * 64 + cand[3 * r1 + 2];
        bool m0 = (cf0 == f), m1 = (cf1 == f);
        float s0 = 0.f, s1 = 0.f;
        #pragma unroll
        for (int ni = 0; ni < 4; ++ni) {
            int n0 = bn + wn * 32 + ni * 8 + 2 * c;
            float bi0 = biasf[n0], bi1 = biasf[n0 + 1];
            float kp0 = keepf[n0], kp1 = keepf[n0 + 1];
            float v00 = (acc[mi][ni][0] + bi0) * kp0;
            float v01 = (acc[mi][ni][1] + bi1) * kp1;
            float v10 = (acc[mi][ni][2] + bi0) * kp0;
            float v11 = (acc[mi][ni][3] + bi1) * kp1;
            if (m0 && cn0 == n0)     v00 = 0.f;
            if (m0 && cn0 == n0 + 1) v01 = 0.f;
            if (m1 && cn1 == n0)     v10 = 0.f;
            if (m1 && cn1 == n0 + 1) v11 = 0.f;
            dst[(size_t)r0 * NN + n0]     = __uint_as_float(tf32r(v00));
            dst[(size_t)r0 * NN + n0 + 1] = __uint_as_float(tf32r(v01));
            dst[(size_t)r1 * NN + n0]     = __uint_as_float(tf32r(v10));
            dst[(size_t)r1 * NN + n0 + 1] = __uint_as_float(tf32r(v11));
            s0 += v00 + v01;
            s1 += v10 + v11;
        }
        s0 += __shfl_xor_sync(0xffffffffu, s0, 1);
        s0 += __shfl_xor_sync(0xffffffffu, s0, 2);
        s1 += __shfl_xor_sync(0xffffffffu, s1, 1);
        s1 += __shfl_xor_sync(0xffffffffu, s1, 2);
        if (c == 0) {
            int lr0 = wm * 64 + mi * 16 + g;
            red[wn * 128 + lr0] = s0;
            red[wn * 128 + lr0 + 8] = s1;
        }
    }
    __syncthreads();
    if (tid < 128) {
        float t = red[tid] + red[128 + tid] + red[256 + tid] + red[384 + tid];
        g_partial[blockIdx.y * BB + bm + tid] += t;   // exclusive slot per (n-tile,row); stream-ordered across frames
    }
}

__global__ void final_kernel(float* __restrict__ out) {
    int b = blockIdx.x * blockDim.x + threadIdx.x;
    if (b < BB) {
        float t = 0.f;
        #pragma unroll
        for (int j = 0; j < JN; j++) t += g_partial[j * BB + b];
        out[b] = t;
    }
}

extern "C" void kernel_launch(void* const* d_in, const int* in_sizes, int n_in,
                              void* d_out, int out_size) {
    const float* weights = (const float*)d_in[0];
    const float* biases  = (const float*)d_in[1];
    const int*   sel     = (const int*)d_in[2];
    const int*   cand    = (const int*)d_in[3];
    float*       out     = (float*)d_out;

    cudaFuncSetAttribute(gemm_frame, cudaFuncAttributeMaxDynamicSharedMemorySize, 65536);

    init_kernel<<<(FF * NN + 255) / 256, 256>>>();
    scatter_kernel<<<1, 256>>>(sel);
    frame0_kernel<<<BB, 256>>>(biases, cand);

    dim3 grid(BB / BM, NN / BN);   // (8, 18) = 144 CTAs
    for (int f = 1; f < FF; ++f)
        gemm_frame<<<grid, 256, 65536>>>(weights, biases, cand, f);

    final_kernel<<<(BB + 255) / 256, 256>>>(out);
}

// round 3
// speedup vs baseline: 1.6726x; 1.6726x over previous
#include <cuda_runtime.h>
#include <cuda_fp16.h>
#include <cstdint>

#define NN 2304
#define BB 1024
#define FF 32
#define BM 128
#define BN 128
#define BKH 64            // halfs per k-chunk (128 bytes)
#define KT (NN / BKH)     // 36
#define JN (NN / 128)     // 18
#define STAGE 32768       // 16KB A + 16KB B
#define NST 3
#define SMEM_BYTES (NST * STAGE)   // 98304

// device scratch (no allocation allowed)
__device__ __half g_w16[(size_t)(FF - 1) * NN * NN];   // fp16 weights (converted per launch)
__device__ __half g_err[2][(size_t)BB * NN];           // ping-pong activations
__device__ float  g_keep[FF * NN];
__device__ float  g_partial[JN * BB];

__global__ void init_kernel() {
    int i = blockIdx.x * blockDim.x + threadIdx.x;
    if (i < FF * NN) g_keep[i] = 1.0f;
    if (i < JN * BB) g_partial[i] = 0.0f;
}

__global__ void scatter_kernel(const int* __restrict__ sel) {
    int i = threadIdx.x;
    if (i < 256) {
        int f = sel[3 * i];
        int node = sel[3 * i + 1] * 64 + sel[3 * i + 2];
        g_keep[f * NN + node] = 0.0f;
    }
}

// weights fp32 -> fp16 (8 elems/thread, exact grid)
__global__ void __launch_bounds__(256) convert_w(const float* __restrict__ w) {
    size_t i = ((size_t)blockIdx.x * blockDim.x + threadIdx.x) * 8;
    const float4* p = (const float4*)(w + i);
    float4 x = p[0], y = p[1];
    __half2 h[4];
    h[0] = __floats2half2_rn(x.x, x.y);
    h[1] = __floats2half2_rn(x.z, x.w);
    h[2] = __floats2half2_rn(y.x, y.y);
    h[3] = __floats2half2_rn(y.z, y.w);
    *(uint4*)(g_w16 + i) = *(const uint4*)h;
}

__global__ void frame0_kernel(const float* __restrict__ biases, const int* __restrict__ cand) {
    int b = blockIdx.x;
    int cf = cand[3 * b];
    int cn = cand[3 * b + 1] * 64 + cand[3 * b + 2];
    float s = 0.f;
    for (int n = threadIdx.x; n < NN; n += blockDim.x) {
        float v = biases[n] * g_keep[n];
        if (cf == 0 && cn == n) v = 0.f;
        g_err[0][(size_t)b * NN + n] = __float2half_rn(v);
        s += v;
    }
    __shared__ float red[8];
    #pragma unroll
    for (int o = 16; o; o >>= 1) s += __shfl_xor_sync(0xffffffffu, s, o);
    if ((threadIdx.x & 31) == 0) red[threadIdx.x >> 5] = s;
    __syncthreads();
    if (threadIdx.x == 0) {
        float t = 0.f;
        #pragma unroll
        for (int w = 0; w < 8; w++) t += red[w];
        g_partial[b] += t;
    }
}

__global__ void final_kernel(float* __restrict__ out) {
    int b = blockIdx.x * blockDim.x + threadIdx.x;
    if (b < BB) {
        float t = 0.f;
        #pragma unroll
        for (int j = 0; j < JN; j++) t += g_partial[j * BB + b];
        out[b] = t;
    }
}

// One frame: dst = mask( bias_f + src @ W_f^T ), fused row sums.
// fp16 mma.m16n8k16, fp32 accumulate, ldmatrix fragments, 3-stage cp.async.
__global__ void __launch_bounds__(256, 1)
gemm_frame(const float* __restrict__ biases, const int* __restrict__ cand, int f)
{
    extern __shared__ char smem[];
    uint32_t sb;
    asm("{ .reg .u64 t; cvta.to.shared.u64 t, %1; cvt.u32.u64 %0, t; }" : "=r"(sb) : "l"(smem));

    const __half* __restrict__ src = g_err[(f + 1) & 1];
    const __half* __restrict__ Wf  = g_w16 + (size_t)(f - 1) * NN * NN;
    __half* __restrict__ dst       = g_err[f & 1];
    const float* __restrict__ biasf = biases + (size_t)f * NN;
    const float* __restrict__ keepf = g_keep + f * NN;

    int tid = threadIdx.x;
    int lane = tid & 31, warp = tid >> 5;
    int g = lane >> 2, c = lane & 3;
    int wm = warp >> 2, wn = warp & 3;     // 2x4 warps, warp tile 64x32
    int bm = blockIdx.x * BM;
    int bn = blockIdx.y * BN;

    // ---- cp.async mapping: 4 x 16B per thread per tile ----
    int lrow = tid >> 3;                   // 0..31
    int lg = tid & 7;                      // 16B chunk within 128B row
    const __half* gA = src + (size_t)(bm + lrow) * NN + lg * 8;
    const __half* gB = Wf + (size_t)(bn + lrow) * NN + lg * 8;
    uint32_t sAoff = (uint32_t)(lrow * 128 + ((lg ^ (lrow & 7)) << 4));

    // ---- ldmatrix per-lane components ----
    int lrow16 = lane & 15;
    int lhalf = lane >> 4;
    int sw = lane & 7;
    uint32_t rowAoff[4], rowBoff[2];
    #pragma unroll
    for (int mi = 0; mi < 4; mi++) rowAoff[mi] = (uint32_t)((wm * 64 + mi * 16 + lrow16) * 128);
    #pragma unroll
    for (int nj = 0; nj < 2; nj++) rowBoff[nj] = (uint32_t)((wn * 32 + nj * 16 + lrow16) * 128);

    float acc[4][4][4];
    #pragma unroll
    for (int mi = 0; mi < 4; mi++)
        #pragma unroll
        for (int ni = 0; ni < 4; ni++)
            #pragma unroll
            for (int r = 0; r < 4; r++) acc[mi][ni][r] = 0.f;

    auto issue = [&](int kt) {
        uint32_t base = sb + (uint32_t)(kt % NST) * STAGE;
        const __half* a = gA + kt * BKH;
        const __half* b = gB + kt * BKH;
        #pragma unroll
        for (int i = 0; i < 4; i++) {
            asm volatile("cp.async.cg.shared.global [%0], [%1], 16;\n"
                         :: "r"(base + sAoff + i * 4096u), "l"(a + (size_t)i * 32 * NN));
            asm volatile("cp.async.cg.shared.global [%0], [%1], 16;\n"
                         :: "r"(base + 16384u + sAoff + i * 4096u), "l"(b + (size_t)i * 32 * NN));
        }
        asm volatile("cp.async.commit_group;\n");
    };

    issue(0);
    issue(1);

    for (int kt = 0; kt < KT; ++kt) {
        if (kt < KT - 1) asm volatile("cp.async.wait_group 1;\n" ::: "memory");
        else             asm volatile("cp.async.wait_group 0;\n" ::: "memory");
        __syncthreads();
        if (kt + 2 < KT) issue(kt + 2);

        uint32_t aBase = sb + (uint32_t)(kt % NST) * STAGE;
        uint32_t bBase = aBase + 16384u;

        #pragma unroll
        for (int kk = 0; kk < 4; ++kk) {
            uint32_t xoff = (uint32_t)((((kk * 2 + lhalf) ^ sw)) << 4);
            uint32_t a[4][4];
            #pragma unroll
            for (int mi = 0; mi < 4; ++mi)
                asm volatile("ldmatrix.sync.aligned.m8n8.x4.shared.b16 {%0,%1,%2,%3}, [%4];"
                    : "=r"(a[mi][0]), "=r"(a[mi][1]), "=r"(a[mi][2]), "=r"(a[mi][3])
                    : "r"(aBase + rowAoff[mi] + xoff));
            uint32_t b[2][4];
            #pragma unroll
            for (int nj = 0; nj < 2; ++nj)
                asm volatile("ldmatrix.sync.aligned.m8n8.x4.shared.b16 {%0,%1,%2,%3}, [%4];"
                    : "=r"(b[nj][0]), "=r"(b[nj][1]), "=r"(b[nj][2]), "=r"(b[nj][3])
                    : "r"(bBase + rowBoff[nj] + xoff));
            #pragma unroll
            for (int mi = 0; mi < 4; ++mi)
                #pragma unroll
                for (int ni = 0; ni < 4; ++ni) {
                    uint32_t b0 = b[ni >> 1][ni & 1];
                    uint32_t b1 = b[ni >> 1][2 + (ni & 1)];
                    asm volatile(
                        "mma.sync.aligned.m16n8k16.row.col.f32.f16.f16.f32 "
                        "{%0,%1,%2,%3}, {%4,%5,%6,%7}, {%8,%9}, {%0,%1,%2,%3};\n"
                        : "+f"(acc[mi][ni][0]), "+f"(acc[mi][ni][1]),
                          "+f"(acc[mi][ni][2]), "+f"(acc[mi][ni][3])
                        : "r"(a[mi][0]), "r"(a[mi][1]), "r"(a[mi][2]), "r"(a[mi][3]),
                          "r"(b0), "r"(b1));
                }
        }
    }
    __syncthreads();   // before reusing smem for reduction

    float* red = (float*)smem;  // [4][128]
    #pragma unroll
    for (int mi = 0; mi < 4; ++mi) {
        int r0 = bm + wm * 64 + mi * 16 + g;
        int r1 = r0 + 8;
        int cf0 = cand[3 * r0], cn0 = cand[3 * r0 + 1] * 64 + cand[3 * r0 + 2];
        int cf1 = cand[3 * r1], cn1 = cand[3 * r1 + 1] * 64 + cand[3 * r1 + 2];
        bool m0 = (cf0 == f), m1 = (cf1 == f);
        float s0 = 0.f, s1 = 0.f;
        #pragma unroll
        for (int ni = 0; ni < 4; ++ni) {
            int n0 = bn + wn * 32 + ni * 8 + 2 * c;
            float bi0 = biasf[n0], bi1 = biasf[n0 + 1];
            float kp0 = keepf[n0], kp1 = keepf[n0 + 1];
            float v00 = (acc[mi][ni][0] + bi0) * kp0;
            float v01 = (acc[mi][ni][1] + bi1) * kp1;
            float v10 = (acc[mi][ni][2] + bi0) * kp0;
            float v11 = (acc[mi][ni][3] + bi1) * kp1;
            if (m0 && cn0 == n0)     v00 = 0.f;
            if (m0 && cn0 == n0 + 1) v01 = 0.f;
            if (m1 && cn1 == n0)     v10 = 0.f;
            if (m1 && cn1 == n0 + 1) v11 = 0.f;
            *(half2*)(dst + (size_t)r0 * NN + n0) = __floats2half2_rn(v00, v01);
            *(half2*)(dst + (size_t)r1 * NN + n0) = __floats2half2_rn(v10, v11);
            s0 += v00 + v01;
            s1 += v10 + v11;
        }
        s0 += __shfl_xor_sync(0xffffffffu, s0, 1);
        s0 += __shfl_xor_sync(0xffffffffu, s0, 2);
        s1 += __shfl_xor_sync(0xffffffffu, s1, 1);
        s1 += __shfl_xor_sync(0xffffffffu, s1, 2);
        if (c == 0) {
            int lr0 = wm * 64 + mi * 16 + g;
            red[wn * 128 + lr0] = s0;
            red[wn * 128 + lr0 + 8] = s1;
        }
    }
    __syncthreads();
    if (tid < 128) {
        float t = red[tid] + red[128 + tid] + red[256 + tid] + red[384 + tid];
        g_partial[blockIdx.y * BB + bm + tid] += t;   // exclusive slot, stream-ordered
    }
}

extern "C" void kernel_launch(void* const* d_in, const int* in_sizes, int n_in,
                              void* d_out, int out_size) {
    const float* weights = (const float*)d_in[0];
    const float* biases  = (const float*)d_in[1];
    const int*   sel     = (const int*)d_in[2];
    const int*   cand    = (const int*)d_in[3];
    float*       out     = (float*)d_out;

    cudaFuncSetAttribute(gemm_frame, cudaFuncAttributeMaxDynamicSharedMemorySize, SMEM_BYTES);

    init_kernel<<<(FF * NN + 255) / 256, 256>>>();
    scatter_kernel<<<1, 256>>>(sel);

    // fp32 -> fp16 weight conversion: 31*2304*2304 / 8 / 256 blocks (exact)
    size_t wtot = (size_t)(FF - 1) * NN * NN;
    convert_w<<<(unsigned)(wtot / 8 / 256), 256>>>(weights);

    frame0_kernel<<<BB, 256>>>(biases, cand);

    dim3 grid(BB / BM, NN / BN);   // (8, 18) = 144 CTAs
    for (int f = 1; f < FF; ++f)
        gemm_frame<<<grid, 256, SMEM_BYTES>>>(biases, cand, f);

    final_kernel<<<(BB + 255) / 256, 256>>>(out);
}

// round 4
// speedup vs baseline: 1.7230x; 1.0301x over previous
#include <cuda_runtime.h>
#include <cuda_fp16.h>
#include <cstdint>

#define NN 2304
#define BB 1024
#define FF 32
#define BM 128
#define BN 128
#define BKH 64            // halfs per k-chunk (128 bytes)
#define KT (NN / BKH)     // 36
#define JN (NN / 128)     // 18
#define STAGE 32768       // 16KB A + 16KB B
#define NST 3
#define SMEM_BYTES (NST * STAGE)   // 98304

// device scratch (no allocation allowed)
__device__ __half g_w16[(size_t)(FF - 1) * NN * NN];   // fp16 weights (converted per launch)
__device__ __half g_err[2][(size_t)BB * NN];           // ping-pong activations
__device__ float  g_keep[FF * NN];
__device__ float  g_partial[JN * BB];

__global__ void init_kernel() {
    int i = blockIdx.x * blockDim.x + threadIdx.x;
    if (i < FF * NN) g_keep[i] = 1.0f;
    if (i < JN * BB) g_partial[i] = 0.0f;
}

__global__ void scatter_kernel(const int* __restrict__ sel) {
    int i = threadIdx.x;
    if (i < 256) {
        int f = sel[3 * i];
        int node = sel[3 * i + 1] * 64 + sel[3 * i + 2];
        g_keep[f * NN + node] = 0.0f;
    }
}

// weights fp32 -> fp16 (8 elems/thread, exact grid)
__global__ void __launch_bounds__(256) convert_w(const float* __restrict__ w) {
    size_t i = ((size_t)blockIdx.x * blockDim.x + threadIdx.x) * 8;
    const float4* p = (const float4*)(w + i);
    float4 x = p[0], y = p[1];
    __half2 h[4];
    h[0] = __floats2half2_rn(x.x, x.y);
    h[1] = __floats2half2_rn(x.z, x.w);
    h[2] = __floats2half2_rn(y.x, y.y);
    h[3] = __floats2half2_rn(y.z, y.w);
    *(uint4*)(g_w16 + i) = *(const uint4*)h;
}

__global__ void frame0_kernel(const float* __restrict__ biases, const int* __restrict__ cand) {
    int b = blockIdx.x;
    int cf = cand[3 * b];
    int cn = cand[3 * b + 1] * 64 + cand[3 * b + 2];
    float s = 0.f;
    for (int n = threadIdx.x; n < NN; n += blockDim.x) {
        float v = biases[n] * g_keep[n];
        if (cf == 0 && cn == n) v = 0.f;
        g_err[0][(size_t)b * NN + n] = __float2half_rn(v);
        s += v;
    }
    __shared__ float red[8];
    #pragma unroll
    for (int o = 16; o; o >>= 1) s += __shfl_xor_sync(0xffffffffu, s, o);
    if ((threadIdx.x & 31) == 0) red[threadIdx.x >> 5] = s;
    __syncthreads();
    if (threadIdx.x == 0) {
        float t = 0.f;
        #pragma unroll
        for (int w = 0; w < 8; w++) t += red[w];
        g_partial[b] += t;
    }
}

__global__ void final_kernel(float* __restrict__ out) {
    int b = blockIdx.x * blockDim.x + threadIdx.x;
    if (b < BB) {
        float t = 0.f;
        #pragma unroll
        for (int j = 0; j < JN; j++) t += g_partial[j * BB + b];
        out[b] = t;
    }
}

// One frame: dst = mask( bias_f + src @ W_f^T ), fused row sums.
// 512 threads, 16 warps (4x4 grid), warp tile 32x32, fp16 mma, 3-stage cp.async.
__global__ void __launch_bounds__(512, 1)
gemm_frame(const float* __restrict__ biases, const int* __restrict__ cand, int f)
{
    extern __shared__ char smem[];
    uint32_t sb;
    asm("{ .reg .u64 t; cvta.to.shared.u64 t, %1; cvt.u32.u64 %0, t; }" : "=r"(sb) : "l"(smem));

    const __half* __restrict__ src = g_err[(f + 1) & 1];
    const __half* __restrict__ Wf  = g_w16 + (size_t)(f - 1) * NN * NN;
    __half* __restrict__ dst       = g_err[f & 1];
    const float* __restrict__ biasf = biases + (size_t)f * NN;
    const float* __restrict__ keepf = g_keep + f * NN;

    int tid = threadIdx.x;
    int lane = tid & 31, warp = tid >> 5;
    int g = lane >> 2, c = lane & 3;
    int wm = warp >> 2, wn = warp & 3;     // 4x4 warps, warp tile 32x32
    int bm = blockIdx.x * BM;
    int bn = blockIdx.y * BN;

    // ---- cp.async mapping: 2 x 16B per thread per tile (A and B each) ----
    int lrow = tid >> 3;                   // 0..63
    int lg = tid & 7;                      // 16B chunk within 128B row
    const __half* gA = src + (size_t)(bm + lrow) * NN + lg * 8;
    const __half* gB = Wf + (size_t)(bn + lrow) * NN + lg * 8;
    uint32_t sAoff = (uint32_t)(lrow * 128 + ((lg ^ (lrow & 7)) << 4));

    // ---- ldmatrix per-lane components ----
    int lrow16 = lane & 15;
    int lhalf = lane >> 4;
    int sw = lane & 7;
    uint32_t rowAoff[2], rowBoff[2];
    #pragma unroll
    for (int mi = 0; mi < 2; mi++) rowAoff[mi] = (uint32_t)((wm * 32 + mi * 16 + lrow16) * 128);
    #pragma unroll
    for (int nj = 0; nj < 2; nj++) rowBoff[nj] = (uint32_t)((wn * 32 + nj * 16 + lrow16) * 128);

    float acc[2][4][4];
    #pragma unroll
    for (int mi = 0; mi < 2; mi++)
        #pragma unroll
        for (int ni = 0; ni < 4; ni++)
            #pragma unroll
            for (int r = 0; r < 4; r++) acc[mi][ni][r] = 0.f;

    auto issue = [&](int kt) {
        uint32_t base = sb + (uint32_t)(kt % NST) * STAGE;
        const __half* a = gA + kt * BKH;
        const __half* b = gB + kt * BKH;
        #pragma unroll
        for (int i = 0; i < 2; i++) {
            asm volatile("cp.async.cg.shared.global [%0], [%1], 16;\n"
                         :: "r"(base + sAoff + i * 8192u), "l"(a + (size_t)i * 64 * NN));
            asm volatile("cp.async.cg.shared.global [%0], [%1], 16;\n"
                         :: "r"(base + 16384u + sAoff + i * 8192u), "l"(b + (size_t)i * 64 * NN));
        }
        asm volatile("cp.async.commit_group;\n");
    };

    issue(0);
    issue(1);

    for (int kt = 0; kt < KT; ++kt) {
        if (kt < KT - 1) asm volatile("cp.async.wait_group 1;\n" ::: "memory");
        else             asm volatile("cp.async.wait_group 0;\n" ::: "memory");
        __syncthreads();
        if (kt + 2 < KT) issue(kt + 2);

        uint32_t aBase = sb + (uint32_t)(kt % NST) * STAGE;
        uint32_t bBase = aBase + 16384u;

        #pragma unroll
        for (int kk = 0; kk < 4; ++kk) {
            uint32_t xoff = (uint32_t)((((kk * 2 + lhalf) ^ sw)) << 4);
            uint32_t a[2][4];
            #pragma unroll
            for (int mi = 0; mi < 2; ++mi)
                asm volatile("ldmatrix.sync.aligned.m8n8.x4.shared.b16 {%0,%1,%2,%3}, [%4];"
                    : "=r"(a[mi][0]), "=r"(a[mi][1]), "=r"(a[mi][2]), "=r"(a[mi][3])
                    : "r"(aBase + rowAoff[mi] + xoff));
            uint32_t b[2][4];
            #pragma unroll
            for (int nj = 0; nj < 2; ++nj)
                asm volatile("ldmatrix.sync.aligned.m8n8.x4.shared.b16 {%0,%1,%2,%3}, [%4];"
                    : "=r"(b[nj][0]), "=r"(b[nj][1]), "=r"(b[nj][2]), "=r"(b[nj][3])
                    : "r"(bBase + rowBoff[nj] + xoff));
            #pragma unroll
            for (int mi = 0; mi < 2; ++mi)
                #pragma unroll
                for (int ni = 0; ni < 4; ++ni) {
                    uint32_t b0 = b[ni >> 1][ni & 1];
                    uint32_t b1 = b[ni >> 1][2 + (ni & 1)];
                    asm volatile(
                        "mma.sync.aligned.m16n8k16.row.col.f32.f16.f16.f32 "
                        "{%0,%1,%2,%3}, {%4,%5,%6,%7}, {%8,%9}, {%0,%1,%2,%3};\n"
                        : "+f"(acc[mi][ni][0]), "+f"(acc[mi][ni][1]),
                          "+f"(acc[mi][ni][2]), "+f"(acc[mi][ni][3])
                        : "r"(a[mi][0]), "r"(a[mi][1]), "r"(a[mi][2]), "r"(a[mi][3]),
                          "r"(b0), "r"(b1));
                }
        }
    }
    __syncthreads();   // before reusing smem for reduction

    float* red = (float*)smem;  // [4][128]
    #pragma unroll
    for (int mi = 0; mi < 2; ++mi) {
        int r0 = bm + wm * 32 + mi * 16 + g;
        int r1 = r0 + 8;
        int cf0 = cand[3 * r0], cn0 = cand[3 * r0 + 1] * 64 + cand[3 * r0 + 2];
        int cf1 = cand[3 * r1], cn1 = cand[3 * r1 + 1] * 64 + cand[3 * r1 + 2];
        bool m0 = (cf0 == f), m1 = (cf1 == f);
        float s0 = 0.f, s1 = 0.f;
        #pragma unroll
        for (int ni = 0; ni < 4; ++ni) {
            int n0 = bn + wn * 32 + ni * 8 + 2 * c;
            float bi0 = biasf[n0], bi1 = biasf[n0 + 1];
            float kp0 = keepf[n0], kp1 = keepf[n0 + 1];
            float v00 = (acc[mi][ni][0] + bi0) * kp0;
            float v01 = (acc[mi][ni][1] + bi1) * kp1;
            float v10 = (acc[mi][ni][2] + bi0) * kp0;
            float v11 = (acc[mi][ni][3] + bi1) * kp1;
            if (m0 && cn0 == n0)     v00 = 0.f;
            if (m0 && cn0 == n0 + 1) v01 = 0.f;
            if (m1 && cn1 == n0)     v10 = 0.f;
            if (m1 && cn1 == n0 + 1) v11 = 0.f;
            *(half2*)(dst + (size_t)r0 * NN + n0) = __floats2half2_rn(v00, v01);
            *(half2*)(dst + (size_t)r1 * NN + n0) = __floats2half2_rn(v10, v11);
            s0 += v00 + v01;
            s1 += v10 + v11;
        }
        s0 += __shfl_xor_sync(0xffffffffu, s0, 1);
        s0 += __shfl_xor_sync(0xffffffffu, s0, 2);
        s1 += __shfl_xor_sync(0xffffffffu, s1, 1);
        s1 += __shfl_xor_sync(0xffffffffu, s1, 2);
        if (c == 0) {
            int lr0 = wm * 32 + mi * 16 + g;
            red[wn * 128 + lr0] = s0;
            red[wn * 128 + lr0 + 8] = s1;
        }
    }
    __syncthreads();
    if (tid < 128) {
        float t = red[tid] + red[128 + tid] + red[256 + tid] + red[384 + tid];
        g_partial[blockIdx.y * BB + bm + tid] += t;   // exclusive slot, stream-ordered
    }
}

extern "C" void kernel_launch(void* const* d_in, const int* in_sizes, int n_in,
                              void* d_out, int out_size) {
    const float* weights = (const float*)d_in[0];
    const float* biases  = (const float*)d_in[1];
    const int*   sel     = (const int*)d_in[2];
    const int*   cand    = (const int*)d_in[3];
    float*       out     = (float*)d_out;

    cudaFuncSetAttribute(gemm_frame, cudaFuncAttributeMaxDynamicSharedMemorySize, SMEM_BYTES);

    init_kernel<<<(FF * NN + 255) / 256, 256>>>();
    scatter_kernel<<<1, 256>>>(sel);

    // fp32 -> fp16 weight conversion: 31*2304*2304 / 8 / 256 blocks (exact)
    size_t wtot = (size_t)(FF - 1) * NN * NN;
    convert_w<<<(unsigned)(wtot / 8 / 256), 256>>>(weights);

    frame0_kernel<<<BB, 256>>>(biases, cand);

    dim3 grid(BB / BM, NN / BN);   // (8, 18) = 144 CTAs
    for (int f = 1; f < FF; ++f)
        gemm_frame<<<grid, 512, SMEM_BYTES>>>(biases, cand, f);

    final_kernel<<<(BB + 255) / 256, 256>>>(out);
}

// round 5
// speedup vs baseline: 1.8025x; 1.0461x over previous
#include <cuda_runtime.h>
#include <cuda_fp16.h>
#include <cstdint>

#define NN 2304
#define BB 1024
#define FF 32
#define BM 128
#define BN 128
#define BKH 64            // halfs per k-chunk (128 bytes)
#define KT (NN / BKH)     // 36
#define JN (NN / 128)     // 18
#define STAGE 32768       // 16KB A + 16KB B
#define NST 3
#define SMEM_BYTES (NST * STAGE)   // 98304
#define WELEMS ((size_t)NN * NN)               // 5308416 per slab
#define CTA_CVT (WELEMS / 144)                 // 36864 elems per CTA
#define THR_CVT (CTA_CVT / 512 / 4)            // 18 float4 per thread

// device scratch (no allocation allowed)
__device__ __half g_w16[(size_t)(FF - 1) * NN * NN];   // fp16 weights (converted in-flight)
__device__ __half g_err[2][(size_t)BB * NN];           // ping-pong activations
__device__ float  g_keep[FF * NN];
__device__ float  g_partial[JN * BB];

__global__ void init_kernel() {
    int i = blockIdx.x * blockDim.x + threadIdx.x;
    if (i < FF * NN) g_keep[i] = 1.0f;
    if (i < JN * BB) g_partial[i] = 0.0f;
}

__global__ void scatter_kernel(const int* __restrict__ sel) {
    int i = threadIdx.x;
    if (i < 256) {
        int f = sel[3 * i];
        int node = sel[3 * i + 1] * 64 + sel[3 * i + 2];
        g_keep[f * NN + node] = 0.0f;
    }
}

// frame0: err0 = mask(bias0), row sums; ALSO converts weight slab 0 to fp16.
__global__ void frame0_kernel(const float* __restrict__ biases, const int* __restrict__ cand,
                              const float* __restrict__ w) {
    int b = blockIdx.x;
    int cf = cand[3 * b];
    int cn = cand[3 * b + 1] * 64 + cand[3 * b + 2];
    float s = 0.f;
    for (int n = threadIdx.x; n < NN; n += blockDim.x) {
        float v = biases[n] * g_keep[n];
        if (cf == 0 && cn == n) v = 0.f;
        g_err[0][(size_t)b * NN + n] = __float2half_rn(v);
        s += v;
    }
    // convert slab 0 (grid-stride over float4s)
    for (size_t i = (size_t)blockIdx.x * blockDim.x + threadIdx.x; i < WELEMS / 4;
         i += (size_t)gridDim.x * blockDim.x) {
        float4 x = ((const float4*)w)[i];
        __half2 h0 = __floats2half2_rn(x.x, x.y);
        __half2 h1 = __floats2half2_rn(x.z, x.w);
        *(uint2*)(g_w16 + i * 4) = make_uint2(*(uint32_t*)&h0, *(uint32_t*)&h1);
    }
    __shared__ float red[8];
    #pragma unroll
    for (int o = 16; o; o >>= 1) s += __shfl_xor_sync(0xffffffffu, s, o);
    if ((threadIdx.x & 31) == 0) red[threadIdx.x >> 5] = s;
    __syncthreads();
    if (threadIdx.x == 0) {
        float t = 0.f;
        #pragma unroll
        for (int wq = 0; wq < 8; wq++) t += red[wq];
        g_partial[b] += t;
    }
}

__global__ void final_kernel(float* __restrict__ out) {
    int b = blockIdx.x * blockDim.x + threadIdx.x;
    if (b < BB) {
        float t = 0.f;
        #pragma unroll
        for (int j = 0; j < JN; j++) t += g_partial[j * BB + b];
        out[b] = t;
    }
}

// One frame: dst = mask( bias_f + src @ W_f^T ), fused row sums.
// ALSO converts fp32 weight slab f -> fp16 (for frame f+1), hidden under HMMA.
__global__ void __launch_bounds__(512, 1)
gemm_frame(const float* __restrict__ biases, const int* __restrict__ cand,
           const float* __restrict__ wraw, int f)
{
    extern __shared__ char smem[];
    uint32_t sb;
    asm("{ .reg .u64 t; cvta.to.shared.u64 t, %1; cvt.u32.u64 %0, t; }" : "=r"(sb) : "l"(smem));

    const __half* __restrict__ src = g_err[(f + 1) & 1];
    const __half* __restrict__ Wf  = g_w16 + (size_t)(f - 1) * NN * NN;
    __half* __restrict__ dst       = g_err[f & 1];
    const float* __restrict__ biasf = biases + (size_t)f * NN;
    const float* __restrict__ keepf = g_keep + f * NN;

    int tid = threadIdx.x;
    int lane = tid & 31, warp = tid >> 5;
    int g = lane >> 2, c = lane & 3;
    int wm = warp >> 2, wn = warp & 3;     // 4x4 warps, warp tile 32x32
    int bm = blockIdx.x * BM;
    int bn = blockIdx.y * BN;

    // ---- in-flight weight conversion (slab f, consumed by frame f+1) ----
    bool do_cvt = (f < FF - 1);
    size_t cvt_base = 0;
    if (do_cvt) {
        int cta = blockIdx.y * 8 + blockIdx.x;   // 0..143
        cvt_base = (size_t)f * WELEMS + (size_t)cta * CTA_CVT + (size_t)tid * 4;
    }
    float4 wv;                                  // value in flight (loaded prev iter)

    // ---- cp.async mapping: 2 x 16B per thread per tile (A and B each) ----
    int lrow = tid >> 3;                   // 0..63
    int lg = tid & 7;                      // 16B chunk within 128B row
    const __half* gA = src + (size_t)(bm + lrow) * NN + lg * 8;
    const __half* gB = Wf + (size_t)(bn + lrow) * NN + lg * 8;
    uint32_t sAoff = (uint32_t)(lrow * 128 + ((lg ^ (lrow & 7)) << 4));

    // ---- ldmatrix per-lane components ----
    int lrow16 = lane & 15;
    int lhalf = lane >> 4;
    int sw = lane & 7;
    uint32_t rowAoff[2], rowBoff[2];
    #pragma unroll
    for (int mi = 0; mi < 2; mi++) rowAoff[mi] = (uint32_t)((wm * 32 + mi * 16 + lrow16) * 128);
    #pragma unroll
    for (int nj = 0; nj < 2; nj++) rowBoff[nj] = (uint32_t)((wn * 32 + nj * 16 + lrow16) * 128);

    float acc[2][4][4];
    #pragma unroll
    for (int mi = 0; mi < 2; mi++)
        #pragma unroll
        for (int ni = 0; ni < 4; ni++)
            #pragma unroll
            for (int r = 0; r < 4; r++) acc[mi][ni][r] = 0.f;

    auto issue = [&](int kt) {
        uint32_t base = sb + (uint32_t)(kt % NST) * STAGE;
        const __half* a = gA + kt * BKH;
        const __half* b = gB + kt * BKH;
        #pragma unroll
        for (int i = 0; i < 2; i++) {
            asm volatile("cp.async.cg.shared.global [%0], [%1], 16;\n"
                         :: "r"(base + sAoff + i * 8192u), "l"(a + (size_t)i * 64 * NN));
            asm volatile("cp.async.cg.shared.global [%0], [%1], 16;\n"
                         :: "r"(base + 16384u + sAoff + i * 8192u), "l"(b + (size_t)i * 64 * NN));
        }
        asm volatile("cp.async.commit_group;\n");
    };

    issue(0);
    issue(1);

    for (int kt = 0; kt < KT; ++kt) {
        if (kt < KT - 1) asm volatile("cp.async.wait_group 1;\n" ::: "memory");
        else             asm volatile("cp.async.wait_group 0;\n" ::: "memory");
        __syncthreads();
        if (kt + 2 < KT) issue(kt + 2);

        // ---- weight-conversion pipeline: store prev iter's load, start next ----
        if (do_cvt) {
            if (kt > 0 && kt <= THR_CVT) {
                size_t e = cvt_base + (size_t)(kt - 1) * 2048;   // 512 thr * 4 elems
                __half2 h0 = __floats2half2_rn(wv.x, wv.y);
                __half2 h1 = __floats2half2_rn(wv.z, wv.w);
                *(uint2*)(g_w16 + e) = make_uint2(*(uint32_t*)&h0, *(uint32_t*)&h1);
            }
            if (kt < THR_CVT)
                wv = __ldg((const float4*)(wraw + cvt_base + (size_t)kt * 2048));
        }

        uint32_t aBase = sb + (uint32_t)(kt % NST) * STAGE;
        uint32_t bBase = aBase + 16384u;

        #pragma unroll
        for (int kk = 0; kk < 4; ++kk) {
            uint32_t xoff = (uint32_t)((((kk * 2 + lhalf) ^ sw)) << 4);
            uint32_t a[2][4];
            #pragma unroll
            for (int mi = 0; mi < 2; ++mi)
                asm volatile("ldmatrix.sync.aligned.m8n8.x4.shared.b16 {%0,%1,%2,%3}, [%4];"
                    : "=r"(a[mi][0]), "=r"(a[mi][1]), "=r"(a[mi][2]), "=r"(a[mi][3])
                    : "r"(aBase + rowAoff[mi] + xoff));
            uint32_t b[2][4];
            #pragma unroll
            for (int nj = 0; nj < 2; ++nj)
                asm volatile("ldmatrix.sync.aligned.m8n8.x4.shared.b16 {%0,%1,%2,%3}, [%4];"
                    : "=r"(b[nj][0]), "=r"(b[nj][1]), "=r"(b[nj][2]), "=r"(b[nj][3])
                    : "r"(bBase + rowBoff[nj] + xoff));
            #pragma unroll
            for (int mi = 0; mi < 2; ++mi)
                #pragma unroll
                for (int ni = 0; ni < 4; ++ni) {
                    uint32_t b0 = b[ni >> 1][ni & 1];
                    uint32_t b1 = b[ni >> 1][2 + (ni & 1)];
                    asm volatile(
                        "mma.sync.aligned.m16n8k16.row.col.f32.f16.f16.f32 "
                        "{%0,%1,%2,%3}, {%4,%5,%6,%7}, {%8,%9}, {%0,%1,%2,%3};\n"
                        : "+f"(acc[mi][ni][0]), "+f"(acc[mi][ni][1]),
                          "+f"(acc[mi][ni][2]), "+f"(acc[mi][ni][3])
                        : "r"(a[mi][0]), "r"(a[mi][1]), "r"(a[mi][2]), "r"(a[mi][3]),
                          "r"(b0), "r"(b1));
                }
        }
    }
    // drain conversion (last loaded float4)
    if (do_cvt) {
        size_t e = cvt_base + (size_t)(THR_CVT - 1) * 2048;
        __half2 h0 = __floats2half2_rn(wv.x, wv.y);
        __half2 h1 = __floats2half2_rn(wv.z, wv.w);
        *(uint2*)(g_w16 + e) = make_uint2(*(uint32_t*)&h0, *(uint32_t*)&h1);
    }
    __syncthreads();   // before reusing smem for reduction

    float* red = (float*)smem;  // [4][128]
    #pragma unroll
    for (int mi = 0; mi < 2; ++mi) {
        int r0 = bm + wm * 32 + mi * 16 + g;
        int r1 = r0 + 8;
        int cf0 = cand[3 * r0], cn0 = cand[3 * r0 + 1] * 64 + cand[3 * r0 + 2];
        int cf1 = cand[3 * r1], cn1 = cand[3 * r1 + 1] * 64 + cand[3 * r1 + 2];
        bool m0 = (cf0 == f), m1 = (cf1 == f);
        float s0 = 0.f, s1 = 0.f;
        #pragma unroll
        for (int ni = 0; ni < 4; ++ni) {
            int n0 = bn + wn * 32 + ni * 8 + 2 * c;
            float bi0 = biasf[n0], bi1 = biasf[n0 + 1];
            float kp0 = keepf[n0], kp1 = keepf[n0 + 1];
            float v00 = (acc[mi][ni][0] + bi0) * kp0;
            float v01 = (acc[mi][ni][1] + bi1) * kp1;
            float v10 = (acc[mi][ni][2] + bi0) * kp0;
            float v11 = (acc[mi][ni][3] + bi1) * kp1;
            if (m0 && cn0 == n0)     v00 = 0.f;
            if (m0 && cn0 == n0 + 1) v01 = 0.f;
            if (m1 && cn1 == n0)     v10 = 0.f;
            if (m1 && cn1 == n0 + 1) v11 = 0.f;
            *(half2*)(dst + (size_t)r0 * NN + n0) = __floats2half2_rn(v00, v01);
            *(half2*)(dst + (size_t)r1 * NN + n0) = __floats2half2_rn(v10, v11);
            s0 += v00 + v01;
            s1 += v10 + v11;
        }
        s0 += __shfl_xor_sync(0xffffffffu, s0, 1);
        s0 += __shfl_xor_sync(0xffffffffu, s0, 2);
        s1 += __shfl_xor_sync(0xffffffffu, s1, 1);
        s1 += __shfl_xor_sync(0xffffffffu, s1, 2);
        if (c == 0) {
            int lr0 = wm * 32 + mi * 16 + g;
            red[wn * 128 + lr0] = s0;
            red[wn * 128 + lr0 + 8] = s1;
        }
    }
    __syncthreads();
    if (tid < 128) {
        float t = red[tid] + red[128 + tid] + red[256 + tid] + red[384 + tid];
        g_partial[blockIdx.y * BB + bm + tid] += t;   // exclusive slot, stream-ordered
    }
}

extern "C" void kernel_launch(void* const* d_in, const int* in_sizes, int n_in,
                              void* d_out, int out_size) {
    const float* weights = (const float*)d_in[0];
    const float* biases  = (const float*)d_in[1];
    const int*   sel     = (const int*)d_in[2];
    const int*   cand    = (const int*)d_in[3];
    float*       out     = (float*)d_out;

    cudaFuncSetAttribute(gemm_frame, cudaFuncAttributeMaxDynamicSharedMemorySize, SMEM_BYTES);

    init_kernel<<<(FF * NN + 255) / 256, 256>>>();
    scatter_kernel<<<1, 256>>>(sel);
    frame0_kernel<<<BB, 256>>>(biases, cand, weights);   // also converts slab 0

    dim3 grid(BB / BM, NN / BN);   // (8, 18) = 144 CTAs
    for (int f = 1; f < FF; ++f)
        gemm_frame<<<grid, 512, SMEM_BYTES>>>(biases, cand, weights, f);

    final_kernel<<<(BB + 255) / 256, 256>>>(out);
}

// round 6
// speedup vs baseline: 4.2072x; 2.3341x over previous
#include <cuda_runtime.h>
#include <cstdint>

#define N 2304
#define BB 1024
#define FF 32
#define NCTA 144
#define NTHR 512

// device scratch (no allocation allowed)
__device__ float g_v[FF * N];      // forward shared state per frame
__device__ float g_z[FF * N];      // backward adjoint per frame
__device__ float g_keep[FF * N];   // keep mask
__device__ int   g_cnt[128];       // grid-barrier counters (one per step)

__global__ void init_kernel() {
    int i = blockIdx.x * blockDim.x + threadIdx.x;
    if (i < FF * N) g_keep[i] = 1.0f;
    if (i < 128) g_cnt[i] = 0;
}

__global__ void scatter_kernel(const int* __restrict__ sel) {
    int i = threadIdx.x;
    if (i < 256) {
        int f = sel[3 * i];
        int node = sel[3 * i + 1] * 64 + sel[3 * i + 2];
        g_keep[f * N + node] = 0.0f;
    }
}

__device__ __forceinline__ void gridbar(int s) {
    __threadfence();
    __syncthreads();
    if (threadIdx.x == 0) {
        atomicAdd(&g_cnt[s], 1);
        volatile int* c = &g_cnt[s];
        while (*c < NCTA) { }
        __threadfence();
    }
    __syncthreads();
}

// Persistent solver: 32 forward matvecs + 31 backward transposed matvecs.
// 144 CTAs x 512 threads, all co-resident (grid <= SM count, 1 small CTA/SM).
__global__ void __launch_bounds__(NTHR, 1)
solve_kernel(const float* __restrict__ W, const float* __restrict__ B)
{
    __shared__ float s_v[N];      // staged vector for current step
    __shared__ float s_red[NTHR];

    int tid = threadIdx.x;
    int cta = blockIdx.x;
    int warp = tid >> 5, lane = tid & 31;
    int bar = 0;

    // ---- v0 = keep_0 * b_0 ----
    if (tid < 16) {
        int row = cta * 16 + tid;
        g_v[row] = g_keep[row] * B[row];
    }
    gridbar(bar++);

    // ---- forward: v_f = keep_f * (b_f + W[f-1] @ v_{f-1}) ----
    for (int f = 1; f < FF; ++f) {
        for (int n = tid; n < N; n += NTHR) s_v[n] = g_v[(f - 1) * N + n];
        __syncthreads();

        int row = cta * 16 + warp;                     // one row per warp
        const float4* wr = (const float4*)(W + ((size_t)(f - 1) * N + row) * N);
        const float4* v4 = (const float4*)s_v;
        float acc = 0.f;
        #pragma unroll
        for (int i = 0; i < 18; ++i) {                 // 576 float4 / 32 lanes
            float4 w4 = wr[lane + i * 32];
            float4 vv = v4[lane + i * 32];
            acc += w4.x * vv.x + w4.y * vv.y + w4.z * vv.z + w4.w * vv.w;
        }
        #pragma unroll
        for (int o = 16; o; o >>= 1) acc += __shfl_xor_sync(0xffffffffu, acc, o);
        if (lane == 0)
            g_v[f * N + row] = g_keep[f * N + row] * (B[f * N + row] + acc);
        gridbar(bar++);
    }

    // ---- z_31 = 1 ----
    if (tid < 16) g_z[31 * N + cta * 16 + tid] = 1.0f;
    gridbar(bar++);

    // ---- backward: z_f = 1 + W[f]^T @ (keep_{f+1} * z_{f+1}) ----
    for (int f = FF - 2; f >= 0; --f) {
        for (int n = tid; n < N; n += NTHR)
            s_v[n] = g_keep[(f + 1) * N + n] * g_z[(f + 1) * N + n];
        __syncthreads();

        int tx = tid & 15, ty = tid >> 4;              // 16 cols x 32 row-lanes
        int col = cta * 16 + tx;
        const float* wp = W + (size_t)f * N * N + col;
        float acc = 0.f;
        #pragma unroll 8
        for (int i = 0; i < 72; ++i) {                 // n = ty + 32*i
            int n = ty + i * 32;
            acc += wp[(size_t)n * N] * s_v[n];
        }
        s_red[tid] = acc;                              // tid = ty*16 + tx
        __syncthreads();
        #pragma unroll
        for (int s2 = 256; s2 >= 16; s2 >>= 1) {
            if (tid < s2) s_red[tid] += s_red[tid + s2];
            __syncthreads();
        }
        if (tid < 16) g_z[f * N + col] = 1.0f + s_red[tid];
        gridbar(bar++);
    }
}

// out[b] = sum_f sum(v_f)  -  v_{cf}[cn] * z_{cf}[cn]
__global__ void final_kernel(const int* __restrict__ cand, float* __restrict__ out) {
    __shared__ float sr[1024];
    int tid = threadIdx.x;
    float t = 0.f;
    for (int i = tid; i < FF * N; i += 1024) t += g_v[i];
    sr[tid] = t;
    __syncthreads();
    #pragma unroll
    for (int s = 512; s; s >>= 1) {
        if (tid < s) sr[tid] += sr[tid + s];
        __syncthreads();
    }
    float TOT = sr[0];
    int cf = cand[3 * tid];
    int cn = cand[3 * tid + 1] * 64 + cand[3 * tid + 2];
    out[tid] = TOT - g_v[cf * N + cn] * g_z[cf * N + cn];
}

extern "C" void kernel_launch(void* const* d_in, const int* in_sizes, int n_in,
                              void* d_out, int out_size) {
    const float* weights = (const float*)d_in[0];
    const float* biases  = (const float*)d_in[1];
    const int*   sel     = (const int*)d_in[2];
    const int*   cand    = (const int*)d_in[3];
    float*       out     = (float*)d_out;

    init_kernel<<<(FF * N + 255) / 256, 256>>>();
    scatter_kernel<<<1, 256>>>(sel);
    solve_kernel<<<NCTA, NTHR>>>(weights, biases);
    final_kernel<<<1, 1024>>>(cand, out);
}

// round 7
// speedup vs baseline: 5.7693x; 1.3713x over previous
#include <cuda_runtime.h>
#include <cstdint>

#define N 2304
#define BB 1024
#define FF 32
#define TEAM 72
#define NCTA (2 * TEAM)
#define NTHR 512

// device scratch (no allocation allowed)
__device__ float g_v[FF * N];       // forward shared state per frame
__device__ float g_z[FF * N];       // backward adjoint per frame
__device__ float g_keep[FF * N];    // keep mask
__device__ float g_vsum[TEAM];      // per-forward-CTA partial of sum_f sum(v_f)
__device__ int   g_cntF[64];        // forward-team barrier counters
__device__ int   g_cntB[64];        // backward-team barrier counters

__global__ void init_kernel() {
    int i = blockIdx.x * blockDim.x + threadIdx.x;
    if (i < FF * N) g_keep[i] = 1.0f;
    if (i < 64) { g_cntF[i] = 0; g_cntB[i] = 0; }
}

__global__ void scatter_kernel(const int* __restrict__ sel) {
    int i = threadIdx.x;
    if (i < 256) {
        int f = sel[3 * i];
        int node = sel[3 * i + 1] * 64 + sel[3 * i + 2];
        g_keep[f * N + node] = 0.0f;
    }
}

__device__ __forceinline__ void teambar(int* cnt, int s) {
    __threadfence();
    __syncthreads();
    if (threadIdx.x == 0) {
        atomicAdd(&cnt[s], 1);
        volatile int* c = &cnt[s];
        while (*c < TEAM) { }
        __threadfence();
    }
    __syncthreads();
}

// Persistent solver: 144 co-resident CTAs split into two independent teams.
// CTAs 0..71:  forward chain  v_f = keep_f * (b_f + W[f-1] @ v_{f-1})
// CTAs 72..143: backward chain z_f = 1 + W[f]^T @ (keep_{f+1} * z_{f+1})
__global__ void __launch_bounds__(NTHR, 1)
solve_kernel(const float* __restrict__ W, const float* __restrict__ B)
{
    __shared__ float s_v[N];
    __shared__ float s_red[NTHR];

    int tid = threadIdx.x;
    int cta = blockIdx.x;
    int warp = tid >> 5, lane = tid & 31;

    if (cta < TEAM) {
        // ================= FORWARD TEAM =================
        int r0 = cta * 32;                       // 32 rows per CTA
        float myacc = 0.f;                       // local contribution to sum_f sum(v_f)

        // v0 = keep_0 * b_0
        if (tid < 32) {
            int row = r0 + tid;
            float v = g_keep[row] * B[row];
            g_v[row] = v;
            myacc += v;
        }
        teambar(g_cntF, 0);

        for (int f = 1; f < FF; ++f) {
            for (int n = tid; n < N; n += NTHR) s_v[n] = g_v[(f - 1) * N + n];
            __syncthreads();

            int ra = r0 + warp * 2;              // 16 warps x 2 rows
            const float4* wa = (const float4*)(W + ((size_t)(f - 1) * N + ra) * N);
            const float4* wb = (const float4*)(W + ((size_t)(f - 1) * N + ra + 1) * N);
            const float4* v4 = (const float4*)s_v;
            float acc0 = 0.f, acc1 = 0.f;
            #pragma unroll
            for (int i = 0; i < 18; ++i) {       // 576 float4 / 32 lanes
                int idx = lane + i * 32;
                float4 vv = v4[idx];
                float4 a4 = wa[idx];
                float4 b4 = wb[idx];
                acc0 += a4.x * vv.x + a4.y * vv.y + a4.z * vv.z + a4.w * vv.w;
                acc1 += b4.x * vv.x + b4.y * vv.y + b4.z * vv.z + b4.w * vv.w;
            }
            #pragma unroll
            for (int o = 16; o; o >>= 1) {
                acc0 += __shfl_xor_sync(0xffffffffu, acc0, o);
                acc1 += __shfl_xor_sync(0xffffffffu, acc1, o);
            }
            if (lane == 0) {
                float va = g_keep[f * N + ra]     * (B[f * N + ra]     + acc0);
                float vb = g_keep[f * N + ra + 1] * (B[f * N + ra + 1] + acc1);
                g_v[f * N + ra]     = va;
                g_v[f * N + ra + 1] = vb;
                myacc += va + vb;
            }
            if (f < FF - 1) teambar(g_cntF, f);
        }

        // block-reduce myacc (fixed tree -> deterministic)
        #pragma unroll
        for (int o = 16; o; o >>= 1) myacc += __shfl_xor_sync(0xffffffffu, myacc, o);
        if (lane == 0) s_red[warp] = myacc;
        __syncthreads();
        if (tid == 0) {
            float t = 0.f;
            #pragma unroll
            for (int w = 0; w < 16; ++w) t += s_red[w];
            g_vsum[cta] = t;
        }
    } else {
        // ================= BACKWARD TEAM =================
        int id = cta - TEAM;
        int c0 = id * 32;                        // 32 cols per CTA

        if (tid < 32) g_z[31 * N + c0 + tid] = 1.0f;
        teambar(g_cntB, 0);

        for (int f = FF - 2; f >= 0; --f) {
            for (int n = tid; n < N; n += NTHR)
                s_v[n] = g_keep[(f + 1) * N + n] * g_z[(f + 1) * N + n];
            __syncthreads();

            int tx = tid & 31, ty = tid >> 5;    // 32 cols x 16 row-lanes
            const float* wp = W + (size_t)f * N * N + c0 + tx;
            float a0 = 0.f, a1 = 0.f, a2 = 0.f, a3 = 0.f;
            #pragma unroll 4
            for (int i = 0; i < 144; i += 4) {   // n = ty + 16*i
                int n0 = ty + (i + 0) * 16;
                int n1 = ty + (i + 1) * 16;
                int n2 = ty + (i + 2) * 16;
                int n3 = ty + (i + 3) * 16;
                a0 += wp[(size_t)n0 * N] * s_v[n0];
                a1 += wp[(size_t)n1 * N] * s_v[n1];
                a2 += wp[(size_t)n2 * N] * s_v[n2];
                a3 += wp[(size_t)n3 * N] * s_v[n3];
            }
            s_red[tid] = (a0 + a1) + (a2 + a3);
            __syncthreads();
            #pragma unroll
            for (int s2 = 256; s2 >= 32; s2 >>= 1) {
                if (tid < s2) s_red[tid] += s_red[tid + s2];
                __syncthreads();
            }
            if (tid < 32) g_z[f * N + c0 + tid] = 1.0f + s_red[tid];
            if (f > 0) teambar(g_cntB, 31 - f);
        }
    }
}

// out[b] = TOT - v_{cf}[cn] * z_{cf}[cn]
__global__ void final_kernel(const int* __restrict__ cand, float* __restrict__ out) {
    __shared__ float s_tot;
    int tid = threadIdx.x;
    if (tid == 0) {
        float t = 0.f;
        #pragma unroll
        for (int i = 0; i < TEAM; ++i) t += g_vsum[i];
        s_tot = t;
    }
    __syncthreads();
    float TOT = s_tot;
    int cf = cand[3 * tid];
    int cn = cand[3 * tid + 1] * 64 + cand[3 * tid + 2];
    out[tid] = TOT - g_v[cf * N + cn] * g_z[cf * N + cn];
}

extern "C" void kernel_launch(void* const* d_in, const int* in_sizes, int n_in,
                              void* d_out, int out_size) {
    const float* weights = (const float*)d_in[0];
    const float* biases  = (const float*)d_in[1];
    const int*   sel     = (const int*)d_in[2];
    const int*   cand    = (const int*)d_in[3];
    float*       out     = (float*)d_out;

    init_kernel<<<(FF * N + 255) / 256, 256>>>();
    scatter_kernel<<<1, 256>>>(sel);
    solve_kernel<<<NCTA, NTHR>>>(weights, biases);
    final_kernel<<<1, BB>>>(cand, out);
}